// round 5
// baseline (speedup 1.0000x reference)
#include <cuda_runtime.h>
#include <cstdint>

// DotPredictor: out[e] = dot(h[src[e]], h[dst[e]]), D=64 f32.
// 8 lanes per edge, 2 edges per thread, MLP=8.
// R5 change: row gathers use __ldcg (L2-cached, L1-bypass). The gather stream
// has ~0% L1 hit rate, so L1 line fills are pure overhead on the 128B/cyc
// L1TEX data path; .cg removes the fill traffic.

#define VEC_PER_ROW 16   // 16 float4 per 64-float row
#define THREADS 256

__device__ __forceinline__ float dot4(float4 a, float4 b) {
    return a.x*b.x + a.y*b.y + a.z*b.z + a.w*b.w;
}

__global__ __launch_bounds__(THREADS)
void dot_predictor_kernel(const float4* __restrict__ h4,
                          const int2* __restrict__ src2,
                          const int2* __restrict__ dst2,
                          float* __restrict__ out,
                          int n_edges)
{
    int tid   = blockIdx.x * THREADS + threadIdx.x;
    int group = tid >> 3;          // 8 lanes per group; group handles 2 edges
    int lane  = tid & 7;
    int e0    = group * 2;
    if (e0 >= n_edges) return;

    int2 s = __ldg(&src2[group]);  // {src[e0], src[e0+1]} — keep in L1 (line reuse)
    int2 d = __ldg(&dst2[group]);

    const float4* pa0 = h4 + (size_t)s.x * VEC_PER_ROW + lane;
    const float4* pb0 = h4 + (size_t)d.x * VEC_PER_ROW + lane;
    const float4* pa1 = h4 + (size_t)s.y * VEC_PER_ROW + lane;
    const float4* pb1 = h4 + (size_t)d.y * VEC_PER_ROW + lane;

    // 8 independent 16B loads, L1-bypass (no reuse -> no fill overhead)
    float4 a00 = __ldcg(pa0);     float4 a01 = __ldcg(pa0 + 8);
    float4 b00 = __ldcg(pb0);     float4 b01 = __ldcg(pb0 + 8);
    float4 a10 = __ldcg(pa1);     float4 a11 = __ldcg(pa1 + 8);
    float4 b10 = __ldcg(pb1);     float4 b11 = __ldcg(pb1 + 8);

    float p0 = dot4(a00, b00) + dot4(a01, b01);
    float p1 = dot4(a10, b10) + dot4(a11, b11);

    // Reduce within the 8-lane group (xor 4/2/1)
    p0 += __shfl_xor_sync(0xFFFFFFFFu, p0, 4);
    p1 += __shfl_xor_sync(0xFFFFFFFFu, p1, 4);
    p0 += __shfl_xor_sync(0xFFFFFFFFu, p0, 2);
    p1 += __shfl_xor_sync(0xFFFFFFFFu, p1, 2);
    p0 += __shfl_xor_sync(0xFFFFFFFFu, p0, 1);
    p1 += __shfl_xor_sync(0xFFFFFFFFu, p1, 1);

    if (lane == 0) {
        out[e0] = p0;
        if (e0 + 1 < n_edges) out[e0 + 1] = p1;
    }
}

extern "C" void kernel_launch(void* const* d_in, const int* in_sizes, int n_in,
                              void* d_out, int out_size)
{
    const float4* h4   = (const float4*)d_in[0];  // h: [N_NODES, 64] f32
    const int2*   src2 = (const int2*)d_in[1];    // int32 [E], read as int2
    const int2*   dst2 = (const int2*)d_in[2];
    float*        out  = (float*)d_out;           // [E] f32

    int n_edges = in_sizes[1];
    int n_groups = (n_edges + 1) / 2;              // 2 edges per 8-lane group
    long long total_threads = (long long)n_groups * 8;
    int blocks = (int)((total_threads + THREADS - 1) / THREADS);

    dot_predictor_kernel<<<blocks, THREADS>>>(h4, src2, dst2, out, n_edges);
}

// round 6
// speedup vs baseline: 1.0539x; 1.0539x over previous
#include <cuda_runtime.h>
#include <cstdint>

// DotPredictor: out[e] = dot(h[src[e]], h[dst[e]]), D=64 f32.
// 8 lanes per edge, 2 edges per thread per iteration, grid-stride loop with
// index prefetch: next iteration's indices load concurrently with current
// gathers, removing the idx->gather serial chain from the steady state.

#define VEC_PER_ROW 16   // 16 float4 per 64-float row
#define THREADS 256
#define PAIRS_PER_GROUP 4   // each 8-lane group processes 4 edge-pairs

__device__ __forceinline__ float dot4(float4 a, float4 b) {
    return a.x*b.x + a.y*b.y + a.z*b.z + a.w*b.w;
}

__global__ __launch_bounds__(THREADS)
void dot_predictor_kernel(const float4* __restrict__ h4,
                          const int2* __restrict__ src2,
                          const int2* __restrict__ dst2,
                          float* __restrict__ out,
                          int n_edges, int n_groups, int groups_total)
{
    int tid    = blockIdx.x * THREADS + threadIdx.x;
    int gidx   = tid >> 3;          // global group slot
    int lane   = tid & 7;
    int stride = groups_total;      // groups launched (grid-stride)

    int g = gidx;
    if (g >= n_groups) return;

    // Prologue: load first pair's indices
    int2 s = __ldg(&src2[g]);
    int2 d = __ldg(&dst2[g]);

    #pragma unroll
    for (int it = 0; it < PAIRS_PER_GROUP; ++it) {
        int g_next = g + stride;
        bool has_next = (it + 1 < PAIRS_PER_GROUP) && (g_next < n_groups);

        const float4* pa0 = h4 + (size_t)s.x * VEC_PER_ROW + lane;
        const float4* pb0 = h4 + (size_t)d.x * VEC_PER_ROW + lane;
        const float4* pa1 = h4 + (size_t)s.y * VEC_PER_ROW + lane;
        const float4* pb1 = h4 + (size_t)d.y * VEC_PER_ROW + lane;

        // 8 independent 16B gathers (MLP=8)
        float4 a00 = __ldg(pa0);     float4 a01 = __ldg(pa0 + 8);
        float4 b00 = __ldg(pb0);     float4 b01 = __ldg(pb0 + 8);
        float4 a10 = __ldg(pa1);     float4 a11 = __ldg(pa1 + 8);
        float4 b10 = __ldg(pb1);     float4 b11 = __ldg(pb1 + 8);

        // Prefetch next pair's indices while gathers are in flight
        int2 s_next, d_next;
        if (has_next) {
            s_next = __ldg(&src2[g_next]);
            d_next = __ldg(&dst2[g_next]);
        }

        float p0 = dot4(a00, b00) + dot4(a01, b01);
        float p1 = dot4(a10, b10) + dot4(a11, b11);

        p0 += __shfl_xor_sync(0xFFFFFFFFu, p0, 4);
        p1 += __shfl_xor_sync(0xFFFFFFFFu, p1, 4);
        p0 += __shfl_xor_sync(0xFFFFFFFFu, p0, 2);
        p1 += __shfl_xor_sync(0xFFFFFFFFu, p1, 2);
        p0 += __shfl_xor_sync(0xFFFFFFFFu, p0, 1);
        p1 += __shfl_xor_sync(0xFFFFFFFFu, p1, 1);

        int e0 = g * 2;
        if (lane == 0) {
            out[e0] = p0;
            if (e0 + 1 < n_edges) out[e0 + 1] = p1;
        }

        if (!has_next) return;
        g = g_next;
        s = s_next;
        d = d_next;
    }
}

extern "C" void kernel_launch(void* const* d_in, const int* in_sizes, int n_in,
                              void* d_out, int out_size)
{
    const float4* h4   = (const float4*)d_in[0];  // h: [N_NODES, 64] f32
    const int2*   src2 = (const int2*)d_in[1];    // int32 [E], read as int2
    const int2*   dst2 = (const int2*)d_in[2];
    float*        out  = (float*)d_out;           // [E] f32

    int n_edges  = in_sizes[1];
    int n_groups = (n_edges + 1) / 2;             // 2 edges per group-iteration
    // Each launched group slot covers PAIRS_PER_GROUP pairs via grid-stride.
    int groups_total = (n_groups + PAIRS_PER_GROUP - 1) / PAIRS_PER_GROUP;
    long long total_threads = (long long)groups_total * 8;
    int blocks = (int)((total_threads + THREADS - 1) / THREADS);

    dot_predictor_kernel<<<blocks, THREADS>>>(h4, src2, dst2, out,
                                              n_edges, n_groups, groups_total);
}